// round 1
// baseline (speedup 1.0000x reference)
#include <cuda_runtime.h>

// Problem constants
#define MM   1024      // checks
#define NN   2048      // vars
#define DVV  3
#define DCC  6
#define DD   8
#define BB   128       // batch
#define TT   5         // iterations
#define CINC 48        // DC*D
#define CINP 52        // padded stride for transposed W1 in smem (16B-mult, 4-way stores)
#define VINV 25        // DV*D + 1
#define VINP 28        // padded var width (16B-mult)
#define HCC  192
#define HVV  100

typedef unsigned long long ull;

// Message ping-pong buffers, edge-major for coalesced gather/scatter:
// layout [edge][batch][D] -> per (edge, warp of batches) a contiguous 4KB span.
__device__ float g_cbuf[(size_t)MM * DCC * BB * DD]; // check->var messages (post syndrome sign)
__device__ float g_vbuf[(size_t)NN * DVV * BB * DD]; // var->check messages

__device__ __forceinline__ ull ffma2(ull a, ull b, ull c) {
    ull d; asm("fma.rn.f32x2 %0, %1, %2, %3;" : "=l"(d) : "l"(a), "l"(b), "l"(c)); return d;
}
__device__ __forceinline__ ull fmul2(ull a, ull b) {
    ull d; asm("mul.rn.f32x2 %0, %1, %2;" : "=l"(d) : "l"(a), "l"(b)); return d;
}
__device__ __forceinline__ ull pack2(float lo, float hi) {
    ull d; asm("mov.b64 %0, {%1, %2};" : "=l"(d) : "f"(lo), "f"(hi)); return d;
}
__device__ __forceinline__ void unpack2(ull v, float& lo, float& hi) {
    asm("mov.b64 {%0, %1}, %2;" : "=f"(lo), "=f"(hi) : "l"(v));
}
__device__ __forceinline__ float gelu_exact(float v) {
    return 0.5f * v * (1.0f + erff(v * 0.70710678118654752f));
}

// ---------------------------------------------------------------------------
// Check kernel: one block per check m, 128 threads = 128 batch rows.
// x[48] -> h[192] (gelu) -> y[48], y *= syndrome sign, scatter to g_cbuf.
// ---------------------------------------------------------------------------
extern "C" __global__ void __launch_bounds__(128)
chk_kernel(const float* __restrict__ w1, const float* __restrict__ b1,
           const float* __restrict__ w2, const float* __restrict__ b2,
           const int* __restrict__ synd, const float* __restrict__ prior,
           const int* __restrict__ chk_nbrs, const int* __restrict__ v2c,
           int first)
{
    extern __shared__ float sm[];
    float* sW1T = sm;                     // [HCC][CINP]  (transposed, padded)
    float* sW2  = sm + HCC * CINP;        // [HCC][CINC]  (row-major as stored)
    float* sB1  = sW2 + HCC * CINC;       // [HCC]
    float* sB2  = sB1 + HCC;              // [CINC]
    int*   sIdx = (int*)(sB2 + CINC);     // [DCC]

    const int m = blockIdx.x, tid = threadIdx.x;
    const float* w1g = w1 + (size_t)m * CINC * HCC;
    const float* w2g = w2 + (size_t)m * HCC * CINC;

    for (int k = tid; k < CINC * HCC; k += 128) {
        int i = k / HCC, j = k - i * HCC;
        sW1T[j * CINP + i] = w1g[k];      // transpose: row j contiguous over i
        sW2[k] = w2g[k];                  // already row j contiguous over o
    }
    for (int k = tid; k < HCC; k += 128) sB1[k] = b1[(size_t)m * HCC + k];
    if (tid < CINC) sB2[tid] = b2[(size_t)m * CINC + tid];
    if (tid < DCC)  sIdx[tid] = first ? chk_nbrs[m * DCC + tid] : v2c[m * DCC + tid];
    __syncthreads();

    // Load x[48] as 24 packed f32x2
    ull xu[24];
    if (first) {
        #pragma unroll
        for (int q = 0; q < 24; ++q) xu[q] = 0ULL;
        #pragma unroll
        for (int s = 0; s < DCC; ++s) xu[s * 4] = pack2(prior[sIdx[s]], 0.0f);
    } else {
        #pragma unroll
        for (int s = 0; s < DCC; ++s) {
            const ulonglong2* src =
                (const ulonglong2*)(g_vbuf + ((size_t)sIdx[s] * BB + tid) * DD);
            ulonglong2 a = src[0], c = src[1];
            xu[s * 4 + 0] = a.x; xu[s * 4 + 1] = a.y;
            xu[s * 4 + 2] = c.x; xu[s * 4 + 3] = c.y;
        }
    }
    const float sg = 1.0f - 2.0f * (float)synd[(size_t)tid * MM + m];

    // y accumulators (48 floats = 24 f32x2), init with layer-2 bias
    ull yu[24];
    #pragma unroll
    for (int q = 0; q < 24; ++q) yu[q] = pack2(sB2[2 * q], sB2[2 * q + 1]);

    #pragma unroll 2
    for (int j = 0; j < HCC; ++j) {
        const ulonglong2* wr = (const ulonglong2*)(sW1T + j * CINP);
        ull a0 = pack2(sB1[j], 0.0f), a1 = 0ULL;
        #pragma unroll
        for (int q = 0; q < 12; ++q) {
            ulonglong2 w = wr[q];
            a0 = ffma2(xu[2 * q],     w.x, a0);
            a1 = ffma2(xu[2 * q + 1], w.y, a1);
        }
        float l0, h0, l1, h1; unpack2(a0, l0, h0); unpack2(a1, l1, h1);
        float h = gelu_exact((l0 + h0) + (l1 + h1));
        ull hh = pack2(h, h);
        const ulonglong2* w2r = (const ulonglong2*)(sW2 + j * CINC);
        #pragma unroll
        for (int q = 0; q < 12; ++q) {
            ulonglong2 w = w2r[q];
            yu[2 * q]     = ffma2(hh, w.x, yu[2 * q]);
            yu[2 * q + 1] = ffma2(hh, w.y, yu[2 * q + 1]);
        }
    }

    const ull sgp = pack2(sg, sg);
    #pragma unroll
    for (int s = 0; s < DCC; ++s) {
        ulonglong2* dst = (ulonglong2*)(g_cbuf + ((size_t)(m * DCC + s) * BB + tid) * DD);
        ulonglong2 o0, o1;
        o0.x = fmul2(yu[s * 4 + 0], sgp); o0.y = fmul2(yu[s * 4 + 1], sgp);
        o1.x = fmul2(yu[s * 4 + 2], sgp); o1.y = fmul2(yu[s * 4 + 3], sgp);
        dst[0] = o0; dst[1] = o1;
    }
}

// ---------------------------------------------------------------------------
// Var kernel: one block per var n, 128 threads = batch rows.
// x[25(+3 pad)] -> h[100] (gelu) -> out[25]; out[24] = llr, out[0:24] messages.
// ---------------------------------------------------------------------------
extern "C" __global__ void __launch_bounds__(128)
var_kernel(const float* __restrict__ w1, const float* __restrict__ b1,
           const float* __restrict__ w2, const float* __restrict__ b2,
           const float* __restrict__ prior, const int* __restrict__ c2v,
           float* __restrict__ out_t)
{
    extern __shared__ float sm[];
    float* sW1T = sm;                    // [HVV][VINP]
    float* sW2  = sm + HVV * VINP;       // [HVV][VINP]
    float* sB1  = sW2 + HVV * VINP;      // [HVV]
    float* sB2  = sB1 + HVV;             // [VINP]
    int*   sIdx = (int*)(sB2 + VINP);    // [DVV]

    const int n = blockIdx.x, tid = threadIdx.x;
    const float* w1g = w1 + (size_t)n * VINV * HVV;
    const float* w2g = w2 + (size_t)n * HVV * VINV;

    for (int k = tid; k < VINV * HVV; k += 128) {
        int i = k / HVV, j = k - i * HVV;
        sW1T[j * VINP + i] = w1g[k];
    }
    for (int k = tid; k < HVV * VINV; k += 128) {
        int j = k / VINV, o = k - j * VINV;
        sW2[j * VINP + o] = w2g[k];
    }
    for (int k = tid; k < HVV; k += 128) {
        sB1[k] = b1[(size_t)n * HVV + k];
        sW1T[k * VINP + 25] = 0.0f; sW1T[k * VINP + 26] = 0.0f; sW1T[k * VINP + 27] = 0.0f;
        sW2 [k * VINP + 25] = 0.0f; sW2 [k * VINP + 26] = 0.0f; sW2 [k * VINP + 27] = 0.0f;
    }
    if (tid < VINP) sB2[tid] = (tid < VINV) ? b2[(size_t)n * VINV + tid] : 0.0f;
    if (tid < DVV)  sIdx[tid] = c2v[n * DVV + tid];
    __syncthreads();

    // x[28] packed: 24 gathered message floats + prior + 3 zero pads
    ull xu[14];
    #pragma unroll
    for (int l = 0; l < DVV; ++l) {
        const ulonglong2* src =
            (const ulonglong2*)(g_cbuf + ((size_t)sIdx[l] * BB + tid) * DD);
        ulonglong2 a = src[0], c = src[1];
        xu[l * 4 + 0] = a.x; xu[l * 4 + 1] = a.y;
        xu[l * 4 + 2] = c.x; xu[l * 4 + 3] = c.y;
    }
    xu[12] = pack2(prior[n], 0.0f);
    xu[13] = 0ULL;

    ull yu[14];
    #pragma unroll
    for (int q = 0; q < 14; ++q) yu[q] = pack2(sB2[2 * q], sB2[2 * q + 1]);

    #pragma unroll 2
    for (int j = 0; j < HVV; ++j) {
        const ulonglong2* wr = (const ulonglong2*)(sW1T + j * VINP);
        ull a0 = pack2(sB1[j], 0.0f), a1 = 0ULL;
        #pragma unroll
        for (int q = 0; q < 7; ++q) {
            ulonglong2 w = wr[q];
            a0 = ffma2(xu[2 * q],     w.x, a0);
            a1 = ffma2(xu[2 * q + 1], w.y, a1);
        }
        float l0, h0, l1, h1; unpack2(a0, l0, h0); unpack2(a1, l1, h1);
        float h = gelu_exact((l0 + h0) + (l1 + h1));
        ull hh = pack2(h, h);
        const ulonglong2* w2r = (const ulonglong2*)(sW2 + j * VINP);
        #pragma unroll
        for (int q = 0; q < 7; ++q) {
            ulonglong2 w = w2r[q];
            yu[2 * q]     = ffma2(hh, w.x, yu[2 * q]);
            yu[2 * q + 1] = ffma2(hh, w.y, yu[2 * q + 1]);
        }
    }

    // Scatter messages (var-edge layout), write LLR output
    #pragma unroll
    for (int l = 0; l < DVV; ++l) {
        ulonglong2* dst = (ulonglong2*)(g_vbuf + ((size_t)(n * DVV + l) * BB + tid) * DD);
        ulonglong2 o0, o1;
        o0.x = yu[l * 4 + 0]; o0.y = yu[l * 4 + 1];
        o1.x = yu[l * 4 + 2]; o1.y = yu[l * 4 + 3];
        dst[0] = o0; dst[1] = o1;
    }
    float llr_lo, llr_hi; unpack2(yu[12], llr_lo, llr_hi);
    out_t[(size_t)tid * NN + n] = llr_lo;   // out[t][b][n]
}

// ---------------------------------------------------------------------------
extern "C" void kernel_launch(void* const* d_in, const int* in_sizes, int n_in,
                              void* d_out, int out_size)
{
    const int*   synd  = (const int*)  d_in[0];
    const float* prior = (const float*)d_in[1];
    const float* cw1   = (const float*)d_in[2];
    const float* cb1   = (const float*)d_in[3];
    const float* cw2   = (const float*)d_in[4];
    const float* cb2   = (const float*)d_in[5];
    const float* vw1   = (const float*)d_in[6];
    const float* vb1   = (const float*)d_in[7];
    const float* vw2   = (const float*)d_in[8];
    const float* vb2   = (const float*)d_in[9];
    const int* chk_nbrs = (const int*)d_in[10];
    const int* c2v      = (const int*)d_in[11];
    const int* v2c      = (const int*)d_in[12];
    float* out = (float*)d_out;

    const int CHK_SMEM = (HCC * CINP + HCC * CINC + HCC + CINC) * 4 + DCC * 4;
    const int VAR_SMEM = (HVV * VINP * 2 + HVV + VINP) * 4 + DVV * 4;

    cudaFuncSetAttribute(chk_kernel, cudaFuncAttributeMaxDynamicSharedMemorySize, CHK_SMEM);
    cudaFuncSetAttribute(var_kernel, cudaFuncAttributeMaxDynamicSharedMemorySize, VAR_SMEM);

    for (int t = 0; t < TT; ++t) {
        chk_kernel<<<MM, 128, CHK_SMEM>>>(cw1, cb1, cw2, cb2, synd, prior,
                                          chk_nbrs, v2c, (t == 0) ? 1 : 0);
        var_kernel<<<NN, 128, VAR_SMEM>>>(vw1, vb1, vw2, vb2, prior, c2v,
                                          out + (size_t)t * BB * NN);
    }
}

// round 2
// speedup vs baseline: 1.0308x; 1.0308x over previous
#include <cuda_runtime.h>

// Problem constants
#define MM   1024      // checks
#define NN   2048      // vars
#define DVV  3
#define DCC  6
#define DD   8
#define BB   128       // batch
#define TT   5         // iterations
#define CINC 48        // DC*D
#define CINP 52        // padded stride for transposed W1 in smem
#define VINV 25        // DV*D + 1
#define VINP 28        // padded var width (16B-mult)
#define HCC  192
#define HCH  96        // half of check hidden dim (split across gridDim.y)
#define HVV  100

#define PARTSZ ((size_t)MM * DCC * BB * DD)

typedef unsigned long long ull;

// Message buffers, edge-major for coalesced gather/scatter.
// g_cbuf holds TWO partial halves of the check->var messages (hidden-dim split);
// the var kernel sums them during gather.
__device__ float g_cbuf[2 * PARTSZ];                  // check->var partials
__device__ float g_vbuf[(size_t)NN * DVV * BB * DD];  // var->check messages

__device__ __forceinline__ ull ffma2(ull a, ull b, ull c) {
    ull d; asm("fma.rn.f32x2 %0, %1, %2, %3;" : "=l"(d) : "l"(a), "l"(b), "l"(c)); return d;
}
__device__ __forceinline__ ull fmul2(ull a, ull b) {
    ull d; asm("mul.rn.f32x2 %0, %1, %2;" : "=l"(d) : "l"(a), "l"(b)); return d;
}
__device__ __forceinline__ ull fadd2(ull a, ull b) {
    ull d; asm("add.rn.f32x2 %0, %1, %2;" : "=l"(d) : "l"(a), "l"(b)); return d;
}
__device__ __forceinline__ ull pack2(float lo, float hi) {
    ull d; asm("mov.b64 %0, {%1, %2};" : "=l"(d) : "f"(lo), "f"(hi)); return d;
}
__device__ __forceinline__ void unpack2(ull v, float& lo, float& hi) {
    asm("mov.b64 {%0, %1}, %2;" : "=f"(lo), "=f"(hi) : "l"(v));
}
__device__ __forceinline__ float gelu_exact(float v) {
    return 0.5f * v * (1.0f + erff(v * 0.70710678118654752f));
}

// ---------------------------------------------------------------------------
// Check kernel: grid (MM, 2). Block (m, half) computes hidden units
// [half*96, half*96+96) and writes a PARTIAL y (sign applied; layer-2 bias
// only in half 0) to g_cbuf[half]. 128 threads = 128 batch rows.
// ---------------------------------------------------------------------------
extern "C" __global__ void __launch_bounds__(128, 4)
chk_kernel(const float* __restrict__ w1, const float* __restrict__ b1,
           const float* __restrict__ w2, const float* __restrict__ b2,
           const int* __restrict__ synd, const float* __restrict__ prior,
           const int* __restrict__ chk_nbrs, const int* __restrict__ v2c,
           int first)
{
    extern __shared__ float sm[];
    float* sW1T = sm;                     // [HCH][CINP]  (transposed, padded)
    float* sW2  = sm + HCH * CINP;        // [HCH][CINC]
    float* sB1  = sW2 + HCH * CINC;       // [HCH]
    float* sB2  = sB1 + HCH;              // [CINC] (zeros for half 1)
    int*   sIdx = (int*)(sB2 + CINC);     // [DCC]

    const int m = blockIdx.x, half = blockIdx.y, tid = threadIdx.x;
    const float* w1g = w1 + (size_t)m * CINC * HCC + half * HCH;
    const float* w2g = w2 + (size_t)m * HCC * CINC + (size_t)half * HCH * CINC;

    for (int k = tid; k < CINC * HCH; k += 128) {
        int i = k / HCH, jj = k - i * HCH;
        sW1T[jj * CINP + i] = w1g[i * HCC + jj];   // transpose: row jj contiguous over i
    }
    for (int k = tid; k < HCH * CINC; k += 128) sW2[k] = w2g[k];
    for (int k = tid; k < HCH; k += 128) sB1[k] = b1[(size_t)m * HCC + half * HCH + k];
    if (tid < CINC) sB2[tid] = (half == 0) ? b2[(size_t)m * CINC + tid] : 0.0f;
    if (tid < DCC)  sIdx[tid] = first ? chk_nbrs[m * DCC + tid] : v2c[m * DCC + tid];
    __syncthreads();

    // Load x[48] as 24 packed f32x2
    ull xu[24];
    if (first) {
        #pragma unroll
        for (int q = 0; q < 24; ++q) xu[q] = 0ULL;
        #pragma unroll
        for (int s = 0; s < DCC; ++s) xu[s * 4] = pack2(prior[sIdx[s]], 0.0f);
    } else {
        #pragma unroll
        for (int s = 0; s < DCC; ++s) {
            const ulonglong2* src =
                (const ulonglong2*)(g_vbuf + ((size_t)sIdx[s] * BB + tid) * DD);
            ulonglong2 a = src[0], c = src[1];
            xu[s * 4 + 0] = a.x; xu[s * 4 + 1] = a.y;
            xu[s * 4 + 2] = c.x; xu[s * 4 + 3] = c.y;
        }
    }
    const float sg = 1.0f - 2.0f * (float)synd[(size_t)tid * MM + m];

    // Partial y accumulators (48 floats = 24 f32x2); bias only in half 0
    ull yu[24];
    #pragma unroll
    for (int q = 0; q < 24; ++q) yu[q] = pack2(sB2[2 * q], sB2[2 * q + 1]);

    #pragma unroll 2
    for (int j = 0; j < HCH; ++j) {
        const ulonglong2* wr = (const ulonglong2*)(sW1T + j * CINP);
        ull a0 = pack2(sB1[j], 0.0f), a1 = 0ULL;
        #pragma unroll
        for (int q = 0; q < 12; ++q) {
            ulonglong2 w = wr[q];
            a0 = ffma2(xu[2 * q],     w.x, a0);
            a1 = ffma2(xu[2 * q + 1], w.y, a1);
        }
        float l0, h0, l1, h1; unpack2(a0, l0, h0); unpack2(a1, l1, h1);
        float h = gelu_exact((l0 + h0) + (l1 + h1));
        ull hh = pack2(h, h);
        const ulonglong2* w2r = (const ulonglong2*)(sW2 + j * CINC);
        #pragma unroll
        for (int q = 0; q < 12; ++q) {
            ulonglong2 w = w2r[q];
            yu[2 * q]     = ffma2(hh, w.x, yu[2 * q]);
            yu[2 * q + 1] = ffma2(hh, w.y, yu[2 * q + 1]);
        }
    }

    const ull sgp = pack2(sg, sg);
    float* obuf = g_cbuf + (size_t)half * PARTSZ;
    #pragma unroll
    for (int s = 0; s < DCC; ++s) {
        ulonglong2* dst = (ulonglong2*)(obuf + ((size_t)(m * DCC + s) * BB + tid) * DD);
        ulonglong2 o0, o1;
        o0.x = fmul2(yu[s * 4 + 0], sgp); o0.y = fmul2(yu[s * 4 + 1], sgp);
        o1.x = fmul2(yu[s * 4 + 2], sgp); o1.y = fmul2(yu[s * 4 + 3], sgp);
        dst[0] = o0; dst[1] = o1;
    }
}

// ---------------------------------------------------------------------------
// Var kernel: one block per var n, 128 threads = batch rows.
// Gathers and sums the two check partials, then x[25(+3)] -> h[100] -> out[25].
// ---------------------------------------------------------------------------
extern "C" __global__ void __launch_bounds__(128)
var_kernel(const float* __restrict__ w1, const float* __restrict__ b1,
           const float* __restrict__ w2, const float* __restrict__ b2,
           const float* __restrict__ prior, const int* __restrict__ c2v,
           float* __restrict__ out_t)
{
    extern __shared__ float sm[];
    float* sW1T = sm;                    // [HVV][VINP]
    float* sW2  = sm + HVV * VINP;       // [HVV][VINP]
    float* sB1  = sW2 + HVV * VINP;      // [HVV]
    float* sB2  = sB1 + HVV;             // [VINP]
    int*   sIdx = (int*)(sB2 + VINP);    // [DVV]

    const int n = blockIdx.x, tid = threadIdx.x;
    const float* w1g = w1 + (size_t)n * VINV * HVV;
    const float* w2g = w2 + (size_t)n * HVV * VINV;

    for (int k = tid; k < VINV * HVV; k += 128) {
        int i = k / HVV, j = k - i * HVV;
        sW1T[j * VINP + i] = w1g[k];
    }
    for (int k = tid; k < HVV * VINV; k += 128) {
        int j = k / VINV, o = k - j * VINV;
        sW2[j * VINP + o] = w2g[k];
    }
    for (int k = tid; k < HVV; k += 128) {
        sB1[k] = b1[(size_t)n * HVV + k];
        sW1T[k * VINP + 25] = 0.0f; sW1T[k * VINP + 26] = 0.0f; sW1T[k * VINP + 27] = 0.0f;
        sW2 [k * VINP + 25] = 0.0f; sW2 [k * VINP + 26] = 0.0f; sW2 [k * VINP + 27] = 0.0f;
    }
    if (tid < VINP) sB2[tid] = (tid < VINV) ? b2[(size_t)n * VINV + tid] : 0.0f;
    if (tid < DVV)  sIdx[tid] = c2v[n * DVV + tid];
    __syncthreads();

    // x[28] packed: 24 gathered message floats (sum of the two chk partials)
    // + prior + 3 zero pads
    ull xu[14];
    #pragma unroll
    for (int l = 0; l < DVV; ++l) {
        size_t off = ((size_t)sIdx[l] * BB + tid) * DD;
        const ulonglong2* sA = (const ulonglong2*)(g_cbuf + off);
        const ulonglong2* sB = (const ulonglong2*)(g_cbuf + PARTSZ + off);
        ulonglong2 a0 = sA[0], a1 = sA[1];
        ulonglong2 b0 = sB[0], b1v = sB[1];
        xu[l * 4 + 0] = fadd2(a0.x, b0.x);
        xu[l * 4 + 1] = fadd2(a0.y, b0.y);
        xu[l * 4 + 2] = fadd2(a1.x, b1v.x);
        xu[l * 4 + 3] = fadd2(a1.y, b1v.y);
    }
    xu[12] = pack2(prior[n], 0.0f);
    xu[13] = 0ULL;

    ull yu[14];
    #pragma unroll
    for (int q = 0; q < 14; ++q) yu[q] = pack2(sB2[2 * q], sB2[2 * q + 1]);

    #pragma unroll 2
    for (int j = 0; j < HVV; ++j) {
        const ulonglong2* wr = (const ulonglong2*)(sW1T + j * VINP);
        ull a0 = pack2(sB1[j], 0.0f), a1 = 0ULL;
        #pragma unroll
        for (int q = 0; q < 7; ++q) {
            ulonglong2 w = wr[q];
            a0 = ffma2(xu[2 * q],     w.x, a0);
            a1 = ffma2(xu[2 * q + 1], w.y, a1);
        }
        float l0, h0, l1, h1; unpack2(a0, l0, h0); unpack2(a1, l1, h1);
        float h = gelu_exact((l0 + h0) + (l1 + h1));
        ull hh = pack2(h, h);
        const ulonglong2* w2r = (const ulonglong2*)(sW2 + j * VINP);
        #pragma unroll
        for (int q = 0; q < 7; ++q) {
            ulonglong2 w = w2r[q];
            yu[2 * q]     = ffma2(hh, w.x, yu[2 * q]);
            yu[2 * q + 1] = ffma2(hh, w.y, yu[2 * q + 1]);
        }
    }

    // Scatter messages (var-edge layout), write LLR output
    #pragma unroll
    for (int l = 0; l < DVV; ++l) {
        ulonglong2* dst = (ulonglong2*)(g_vbuf + ((size_t)(n * DVV + l) * BB + tid) * DD);
        ulonglong2 o0, o1;
        o0.x = yu[l * 4 + 0]; o0.y = yu[l * 4 + 1];
        o1.x = yu[l * 4 + 2]; o1.y = yu[l * 4 + 3];
        dst[0] = o0; dst[1] = o1;
    }
    float llr_lo, llr_hi; unpack2(yu[12], llr_lo, llr_hi);
    out_t[(size_t)tid * NN + n] = llr_lo;   // out[t][b][n]
}

// ---------------------------------------------------------------------------
extern "C" void kernel_launch(void* const* d_in, const int* in_sizes, int n_in,
                              void* d_out, int out_size)
{
    const int*   synd  = (const int*)  d_in[0];
    const float* prior = (const float*)d_in[1];
    const float* cw1   = (const float*)d_in[2];
    const float* cb1   = (const float*)d_in[3];
    const float* cw2   = (const float*)d_in[4];
    const float* cb2   = (const float*)d_in[5];
    const float* vw1   = (const float*)d_in[6];
    const float* vb1   = (const float*)d_in[7];
    const float* vw2   = (const float*)d_in[8];
    const float* vb2   = (const float*)d_in[9];
    const int* chk_nbrs = (const int*)d_in[10];
    const int* c2v      = (const int*)d_in[11];
    const int* v2c      = (const int*)d_in[12];
    float* out = (float*)d_out;

    const int CHK_SMEM = (HCH * CINP + HCH * CINC + HCH + CINC) * 4 + DCC * 4;
    const int VAR_SMEM = (HVV * VINP * 2 + HVV + VINP) * 4 + DVV * 4;

    cudaFuncSetAttribute(chk_kernel, cudaFuncAttributeMaxDynamicSharedMemorySize, CHK_SMEM);
    cudaFuncSetAttribute(var_kernel, cudaFuncAttributeMaxDynamicSharedMemorySize, VAR_SMEM);

    dim3 chk_grid(MM, 2);
    for (int t = 0; t < TT; ++t) {
        chk_kernel<<<chk_grid, 128, CHK_SMEM>>>(cw1, cb1, cw2, cb2, synd, prior,
                                                chk_nbrs, v2c, (t == 0) ? 1 : 0);
        var_kernel<<<NN, 128, VAR_SMEM>>>(vw1, vb1, vw2, vb2, prior, c2v,
                                          out + (size_t)t * BB * NN);
    }
}